// round 7
// baseline (speedup 1.0000x reference)
#include <cuda_runtime.h>
#include <math.h>

#define NBINS 30
#define NCELLS (NBINS * NBINS)
#define NFEAT 32          // 16 u-columns + 16 s-columns
#define MMSLOTS 33        // y, u0..15, s0..15

__device__ unsigned int g_hist[NFEAT * NCELLS];
__device__ unsigned int g_min[MMSLOTS];
__device__ unsigned int g_max[MMSLOTS];
__device__ double g_sum_abs;
__device__ double g_mius[16];
__device__ double g_loss;
__device__ unsigned int g_ticket;

// monotone float <-> uint mapping for atomicMin/Max
__device__ __forceinline__ unsigned enc(float f) {
    unsigned u = __float_as_uint(f);
    return (u & 0x80000000u) ? ~u : (u | 0x80000000u);
}
__device__ __forceinline__ float dec(unsigned u) {
    unsigned v = (u & 0x80000000u) ? (u ^ 0x80000000u) : ~u;
    return __uint_as_float(v);
}

__device__ __forceinline__ int binf2(float x, float iv, float bias) {
    int b = (int)floorf(fmaf(x, iv, bias));
    b = b < 0 ? 0 : b;
    return b > (NBINS - 1) ? (NBINS - 1) : b;
}

// ---------------------------------------------------------------- init + mi_us
__global__ void k_init(const float* __restrict__ u, const float* __restrict__ s) {
    int i = blockIdx.x * blockDim.x + threadIdx.x;
    int stride = gridDim.x * blockDim.x;
    for (int j = i; j < NFEAT * NCELLS; j += stride) g_hist[j] = 0u;
    if (i == 0) { g_sum_abs = 0.0; g_loss = 0.0; g_ticket = 0u; }
    if (i < MMSLOTS) { g_min[i] = 0xFFFFFFFFu; g_max[i] = 0u; }

    if (blockIdx.x < 16 && threadIdx.x < 32) {
        int r = blockIdx.x;
        int lane = threadIdx.x;
        int k = lane & 15;                 // sample index 0..15 (lanes 16..31 mirror)
        float uk = u[r * 16 + k];
        float sk = s[r * 16 + k];
        float umn = uk, umx = uk, smn2 = sk, smx2 = sk;
#pragma unroll
        for (int o = 8; o; o >>= 1) {
            umn  = fminf(umn,  __shfl_xor_sync(0xffffffffu, umn,  o));
            umx  = fmaxf(umx,  __shfl_xor_sync(0xffffffffu, umx,  o));
            smn2 = fminf(smn2, __shfl_xor_sync(0xffffffffu, smn2, o));
            smx2 = fmaxf(smx2, __shfl_xor_sync(0xffffffffu, smx2, o));
        }
        float ustep = (umx - umn) / 29.0f;
        float sstep = (smx2 - smn2) / 29.0f;
        int cu = 0, cs = 0;
#pragma unroll
        for (int j = 0; j < 30; j++) {
            float eu = (j == 29) ? umx  : __fadd_rn(umn,  __fmul_rn((float)j, ustep));
            float es = (j == 29) ? smx2 : __fadd_rn(smn2, __fmul_rn((float)j, sstep));
            cu += (eu <= uk);
            cs += (es <= sk);
        }
        int lus[16], lss[16];
#pragma unroll
        for (int m = 0; m < 16; m++) {
            lus[m] = __shfl_sync(0xffffffffu, cu, m);
            lss[m] = __shfl_sync(0xffffffffu, cs, m);
        }
        float mi = 0.0f;
        if (lane < 16) {
            bool first = true;
            for (int m = 0; m < k; m++)
                if (lus[m] == cu && lss[m] == cs) { first = false; break; }
            if (first) {
                int C = 0, A = 0, B = 0;
#pragma unroll
                for (int m = 0; m < 16; m++) {
                    int eq_u = (lus[m] == cu);
                    int eq_s = (lss[m] == cs);
                    C += eq_u & eq_s;
                    A += eq_u;
                    B += eq_s;
                }
                mi = ((float)C * (1.0f / 16.0f)) * __logf(((float)(C * 16)) / ((float)(A * B)));
            }
        }
#pragma unroll
        for (int o = 8; o; o >>= 1) mi += __shfl_xor_sync(0x0000ffffu, mi, o);
        if (lane == 0) g_mius[r] = (double)mi;
    }
}

// ---------------------------------------------------------------- pass 1: min/max + L1
__global__ void __launch_bounds__(256) k_minmax(
    const float* __restrict__ yt, const float* __restrict__ yp,
    const float* __restrict__ u, const float* __restrict__ s, int N)
{
    float ymn = INFINITY, ymx = -INFINITY;
    float umn[16], umx[16], smn[16], smx[16];
#pragma unroll
    for (int f = 0; f < 16; f++) {
        umn[f] = INFINITY; umx[f] = -INFINITY;
        smn[f] = INFINITY; smx[f] = -INFINITY;
    }
    float sab = 0.0f;

    int stride = gridDim.x * blockDim.x;
    for (int i = blockIdx.x * blockDim.x + threadIdx.x; i < N; i += stride) {
        float a = yt[i], b = yp[i];
        sab += fabsf(a - b);
        ymn = fminf(ymn, b); ymx = fmaxf(ymx, b);
        const float4* ur = reinterpret_cast<const float4*>(u) + (size_t)i * 4;
        const float4* sr = reinterpret_cast<const float4*>(s) + (size_t)i * 4;
#pragma unroll
        for (int q = 0; q < 4; q++) {
            float4 uv = ur[q];
            float4 sv = sr[q];
            umn[4*q+0] = fminf(umn[4*q+0], uv.x); umx[4*q+0] = fmaxf(umx[4*q+0], uv.x);
            umn[4*q+1] = fminf(umn[4*q+1], uv.y); umx[4*q+1] = fmaxf(umx[4*q+1], uv.y);
            umn[4*q+2] = fminf(umn[4*q+2], uv.z); umx[4*q+2] = fmaxf(umx[4*q+2], uv.z);
            umn[4*q+3] = fminf(umn[4*q+3], uv.w); umx[4*q+3] = fmaxf(umx[4*q+3], uv.w);
            smn[4*q+0] = fminf(smn[4*q+0], sv.x); smx[4*q+0] = fmaxf(smx[4*q+0], sv.x);
            smn[4*q+1] = fminf(smn[4*q+1], sv.y); smx[4*q+1] = fmaxf(smx[4*q+1], sv.y);
            smn[4*q+2] = fminf(smn[4*q+2], sv.z); smx[4*q+2] = fmaxf(smx[4*q+2], sv.z);
            smn[4*q+3] = fminf(smn[4*q+3], sv.w); smx[4*q+3] = fmaxf(smx[4*q+3], sv.w);
        }
    }

    // gather into one indexed array: [0..32]=mins(y,u,s) [33..65]=maxes [66]=sum
    float all[67];
    all[0] = ymn; all[33] = ymx;
#pragma unroll
    for (int f = 0; f < 16; f++) {
        all[1 + f]  = umn[f]; all[17 + f] = smn[f];
        all[34 + f] = umx[f]; all[50 + f] = smx[f];
    }
    all[66] = sab;

    __shared__ float red[67 * 8];
    int wid = threadIdx.x >> 5, lane = threadIdx.x & 31;
#pragma unroll
    for (int q = 0; q < 67; q++) {
        float v = all[q];
#pragma unroll
        for (int o = 16; o; o >>= 1) {
            float other = __shfl_xor_sync(0xffffffffu, v, o);
            v = (q < 33) ? fminf(v, other) : (q < 66 ? fmaxf(v, other) : v + other);
        }
        if (lane == 0) red[q * 8 + wid] = v;
    }
    __syncthreads();
    if (threadIdx.x < 67) {
        int q = threadIdx.x;
        float v = red[q * 8];
        for (int w = 1; w < 8; w++) {
            float o = red[q * 8 + w];
            v = (q < 33) ? fminf(v, o) : (q < 66 ? fmaxf(v, o) : v + o);
        }
        if (q < 33)       atomicMin(&g_min[q], enc(v));
        else if (q < 66)  atomicMax(&g_max[q - 33], enc(v));
        else              atomicAdd(&g_sum_abs, (double)v);
    }
}

// ---------------------------------------------------------------- pass 2: histograms
// Single pass: all 32 features per CTA, 16-bit packed counters
// (low 16 = u-feature f, high 16 = s-feature f). 57.6 KB smem, 2 CTAs/SM.
// Max cell count for this input ~17.5K << 65535 -> no overflow.
__global__ void __launch_bounds__(1024, 2) k_hist(
    const float* __restrict__ yp, const float* __restrict__ u,
    const float* __restrict__ s, int N)
{
    extern __shared__ unsigned int sh[];   // 16 * NCELLS packed counters
    __shared__ float sinv[MMSLOTS], sbias[MMSLOTS];
    int tid = threadIdx.x;
    if (tid < MMSLOTS) {
        float lo = dec(g_min[tid]);
        float hi = dec(g_max[tid]);
        float iv = (float)NBINS / (hi - lo);
        sinv[tid]  = iv;
        sbias[tid] = -lo * iv;
    }
    for (int j = tid; j < 16 * NCELLS; j += blockDim.x) sh[j] = 0u;
    __syncthreads();

    int stride = gridDim.x * blockDim.x;
    for (int i = blockIdx.x * blockDim.x + tid; i < N; i += stride) {
        float y = yp[i];
        int iy = binf2(y, sinv[0], sbias[0]);
        const float4* ur = reinterpret_cast<const float4*>(u) + (size_t)i * 4;
        const float4* sr = reinterpret_cast<const float4*>(s) + (size_t)i * 4;
#pragma unroll
        for (int q = 0; q < 4; q++) {
            float4 uv = ur[q];
            float4 sv = sr[q];
            float uu[4] = {uv.x, uv.y, uv.z, uv.w};
            float ss[4] = {sv.x, sv.y, sv.z, sv.w};
#pragma unroll
            for (int k = 0; k < 4; k++) {
                int f = 4 * q + k;
                int ixu = binf2(uu[k], sinv[1 + f],  sbias[1 + f]);
                atomicAdd(&sh[f * NCELLS + ixu * NBINS + iy], 1u);
                int ixs = binf2(ss[k], sinv[17 + f], sbias[17 + f]);
                atomicAdd(&sh[f * NCELLS + ixs * NBINS + iy], 0x10000u);
            }
        }
    }
    __syncthreads();
    for (int j = tid; j < 16 * NCELLS; j += blockDim.x) {
        unsigned v = sh[j];
        int f = j / NCELLS, c = j - f * NCELLS;
        if (v & 0xFFFFu)  atomicAdd(&g_hist[f * NCELLS + c], v & 0xFFFFu);
        if (v >> 16)      atomicAdd(&g_hist[(16 + f) * NCELLS + c], v >> 16);
    }
}

// ---------------------------------------------------------------- pass 3: MI per feature + final combine
__global__ void __launch_bounds__(256) k_mi(float* __restrict__ out, int N, int out_size) {
    __shared__ unsigned hcell[NCELLS];
    __shared__ float A[NBINS], B[NBINS];
    __shared__ double wred[8];
    __shared__ unsigned s_ticket;
    int tid = threadIdx.x, w = tid >> 5, lane = tid & 31;
    int f = blockIdx.x;

    const unsigned* h = g_hist + f * NCELLS;
    for (int j = tid; j < NCELLS; j += 256) hcell[j] = h[j];
    __syncthreads();

    if (tid < NBINS) {
        float ra = 0.0f;
#pragma unroll
        for (int j = 0; j < NBINS; j++) ra += (float)hcell[tid * NBINS + j];
        A[tid] = ra;
    } else if (tid >= 64 && tid < 64 + NBINS) {
        int c = tid - 64;
        float rb = 0.0f;
#pragma unroll
        for (int j = 0; j < NBINS; j++) rb += (float)hcell[j * NBINS + c];
        B[c] = rb;
    }
    __syncthreads();

    float invTot = 1.0f / (float)N;
    float mi = 0.0f;
    for (int c = tid; c < NCELLS; c += 256) {
        int i = c / NBINS, j = c - i * NBINS;
        float px = A[i] * invTot; if (px == 0.0f) px = 1e-10f;
        float py = B[j] * invTot; if (py == 0.0f) py = 1e-10f;
        unsigned cc = hcell[c];
        float pxy = cc ? (float)cc * invTot : 1e-10f;
        mi += pxy * __logf(pxy / (px * py));
    }
#pragma unroll
    for (int o = 16; o; o >>= 1) mi += __shfl_xor_sync(0xffffffffu, mi, o);
    if (lane == 0) wred[w] = (double)mi;
    __syncthreads();

    if (tid == 0) {
        double block_mi = 0.0;
        for (int k = 0; k < 8; k++) block_mi += wred[k];
        atomicAdd(&g_loss, 0.1 * block_mi);
        __threadfence();
        s_ticket = atomicAdd(&g_ticket, 1u);
    }
    __syncthreads();

    if (s_ticket == (unsigned)(gridDim.x - 1)) {
        // last block: all other blocks' g_loss contributions are visible
        for (int k = tid + 1; k < out_size; k += 256) out[k] = 0.0f;
        if (tid == 0) {
            double acc = g_loss + g_sum_abs / (double)N;
            for (int r = 0; r < 16; r++) acc -= 0.05 * g_mius[r];
            out[0] = (float)acc;
        }
    }
}

// ---------------------------------------------------------------- launch
extern "C" void kernel_launch(void* const* d_in, const int* in_sizes, int n_in,
                              void* d_out, int out_size) {
    const float* y_true = (const float*)d_in[0];
    const float* y_pred = (const float*)d_in[1];
    // d_in[2] = u_attr, d_in[3] = s_attr  (unused by the reference)
    const float* u_vec  = (const float*)d_in[4];
    const float* s_vec  = (const float*)d_in[5];
    int N = in_sizes[0];

    k_init<<<32, 256>>>(u_vec, s_vec);
    k_minmax<<<1184, 256>>>(y_true, y_pred, u_vec, s_vec, N);

    size_t shbytes = (size_t)16 * NCELLS * sizeof(unsigned);          // 57.6 KB
    cudaFuncSetAttribute(k_hist, cudaFuncAttributeMaxDynamicSharedMemorySize, (int)shbytes);
    k_hist<<<296, 1024, shbytes>>>(y_pred, u_vec, s_vec, N);

    k_mi<<<32, 256>>>((float*)d_out, N, out_size);
}

// round 9
// speedup vs baseline: 1.4291x; 1.4291x over previous
#include <cuda_runtime.h>
#include <math.h>

#define NBINS 30
#define NCELLS (NBINS * NBINS)
#define NFEAT 32          // 16 u-columns + 16 s-columns
#define MMSLOTS 33        // y, u0..15, s0..15

__device__ unsigned int g_hist[NFEAT * NCELLS];
__device__ unsigned int g_min[MMSLOTS];
__device__ unsigned int g_max[MMSLOTS];
__device__ double g_sum_abs;
__device__ double g_mius[16];
__device__ double g_loss;
__device__ unsigned int g_ticket;

// monotone float <-> uint mapping for atomicMin/Max
__device__ __forceinline__ unsigned enc(float f) {
    unsigned u = __float_as_uint(f);
    return (u & 0x80000000u) ? ~u : (u | 0x80000000u);
}
__device__ __forceinline__ float dec(unsigned u) {
    unsigned v = (u & 0x80000000u) ? (u ^ 0x80000000u) : ~u;
    return __uint_as_float(v);
}

__device__ __forceinline__ int binf2(float x, float iv, float bias) {
    int b = (int)floorf(fmaf(x, iv, bias));
    b = b < 0 ? 0 : b;
    return b > (NBINS - 1) ? (NBINS - 1) : b;
}

// ---------------------------------------------------------------- init + mi_us
__global__ void k_init(const float* __restrict__ u, const float* __restrict__ s) {
    int i = blockIdx.x * blockDim.x + threadIdx.x;
    int stride = gridDim.x * blockDim.x;
    for (int j = i; j < NFEAT * NCELLS; j += stride) g_hist[j] = 0u;
    if (i == 0) { g_sum_abs = 0.0; g_loss = 0.0; g_ticket = 0u; }
    if (i < MMSLOTS) { g_min[i] = 0xFFFFFFFFu; g_max[i] = 0u; }

    if (blockIdx.x < 16 && threadIdx.x < 32) {
        int r = blockIdx.x;
        int lane = threadIdx.x;
        int k = lane & 15;                 // sample index 0..15 (lanes 16..31 mirror)
        float uk = u[r * 16 + k];
        float sk = s[r * 16 + k];
        float umn = uk, umx = uk, smn2 = sk, smx2 = sk;
#pragma unroll
        for (int o = 8; o; o >>= 1) {
            umn  = fminf(umn,  __shfl_xor_sync(0xffffffffu, umn,  o));
            umx  = fmaxf(umx,  __shfl_xor_sync(0xffffffffu, umx,  o));
            smn2 = fminf(smn2, __shfl_xor_sync(0xffffffffu, smn2, o));
            smx2 = fmaxf(smx2, __shfl_xor_sync(0xffffffffu, smx2, o));
        }
        float ustep = (umx - umn) / 29.0f;
        float sstep = (smx2 - smn2) / 29.0f;
        int cu = 0, cs = 0;
#pragma unroll
        for (int j = 0; j < 30; j++) {
            float eu = (j == 29) ? umx  : __fadd_rn(umn,  __fmul_rn((float)j, ustep));
            float es = (j == 29) ? smx2 : __fadd_rn(smn2, __fmul_rn((float)j, sstep));
            cu += (eu <= uk);
            cs += (es <= sk);
        }
        int lus[16], lss[16];
#pragma unroll
        for (int m = 0; m < 16; m++) {
            lus[m] = __shfl_sync(0xffffffffu, cu, m);
            lss[m] = __shfl_sync(0xffffffffu, cs, m);
        }
        float mi = 0.0f;
        if (lane < 16) {
            bool first = true;
            for (int m = 0; m < k; m++)
                if (lus[m] == cu && lss[m] == cs) { first = false; break; }
            if (first) {
                int C = 0, A = 0, B = 0;
#pragma unroll
                for (int m = 0; m < 16; m++) {
                    int eq_u = (lus[m] == cu);
                    int eq_s = (lss[m] == cs);
                    C += eq_u & eq_s;
                    A += eq_u;
                    B += eq_s;
                }
                mi = ((float)C * (1.0f / 16.0f)) * __logf(((float)(C * 16)) / ((float)(A * B)));
            }
        }
#pragma unroll
        for (int o = 8; o; o >>= 1) mi += __shfl_xor_sync(0x0000ffffu, mi, o);
        if (lane == 0) g_mius[r] = (double)mi;
    }
}

// ---------------------------------------------------------------- pass 1: min/max + L1
__global__ void __launch_bounds__(256) k_minmax(
    const float* __restrict__ yt, const float* __restrict__ yp,
    const float* __restrict__ u, const float* __restrict__ s, int N)
{
    float ymn = INFINITY, ymx = -INFINITY;
    float umn[16], umx[16], smn[16], smx[16];
#pragma unroll
    for (int f = 0; f < 16; f++) {
        umn[f] = INFINITY; umx[f] = -INFINITY;
        smn[f] = INFINITY; smx[f] = -INFINITY;
    }
    float sab = 0.0f;

    int stride = gridDim.x * blockDim.x;
    for (int i = blockIdx.x * blockDim.x + threadIdx.x; i < N; i += stride) {
        float a = yt[i], b = yp[i];
        sab += fabsf(a - b);
        ymn = fminf(ymn, b); ymx = fmaxf(ymx, b);
        const float4* ur = reinterpret_cast<const float4*>(u) + (size_t)i * 4;
        const float4* sr = reinterpret_cast<const float4*>(s) + (size_t)i * 4;
#pragma unroll
        for (int q = 0; q < 4; q++) {
            float4 uv = ur[q];
            float4 sv = sr[q];
            umn[4*q+0] = fminf(umn[4*q+0], uv.x); umx[4*q+0] = fmaxf(umx[4*q+0], uv.x);
            umn[4*q+1] = fminf(umn[4*q+1], uv.y); umx[4*q+1] = fmaxf(umx[4*q+1], uv.y);
            umn[4*q+2] = fminf(umn[4*q+2], uv.z); umx[4*q+2] = fmaxf(umx[4*q+2], uv.z);
            umn[4*q+3] = fminf(umn[4*q+3], uv.w); umx[4*q+3] = fmaxf(umx[4*q+3], uv.w);
            smn[4*q+0] = fminf(smn[4*q+0], sv.x); smx[4*q+0] = fmaxf(smx[4*q+0], sv.x);
            smn[4*q+1] = fminf(smn[4*q+1], sv.y); smx[4*q+1] = fmaxf(smx[4*q+1], sv.y);
            smn[4*q+2] = fminf(smn[4*q+2], sv.z); smx[4*q+2] = fmaxf(smx[4*q+2], sv.z);
            smn[4*q+3] = fminf(smn[4*q+3], sv.w); smx[4*q+3] = fmaxf(smx[4*q+3], sv.w);
        }
    }

    // gather into one indexed array: [0..32]=mins(y,u,s) [33..65]=maxes [66]=sum
    float all[67];
    all[0] = ymn; all[33] = ymx;
#pragma unroll
    for (int f = 0; f < 16; f++) {
        all[1 + f]  = umn[f]; all[17 + f] = smn[f];
        all[34 + f] = umx[f]; all[50 + f] = smx[f];
    }
    all[66] = sab;

    __shared__ float red[67 * 8];
    int wid = threadIdx.x >> 5, lane = threadIdx.x & 31;
#pragma unroll
    for (int q = 0; q < 67; q++) {
        float v = all[q];
#pragma unroll
        for (int o = 16; o; o >>= 1) {
            float other = __shfl_xor_sync(0xffffffffu, v, o);
            v = (q < 33) ? fminf(v, other) : (q < 66 ? fmaxf(v, other) : v + other);
        }
        if (lane == 0) red[q * 8 + wid] = v;
    }
    __syncthreads();
    if (threadIdx.x < 67) {
        int q = threadIdx.x;
        float v = red[q * 8];
        for (int w = 1; w < 8; w++) {
            float o = red[q * 8 + w];
            v = (q < 33) ? fminf(v, o) : (q < 66 ? fmaxf(v, o) : v + o);
        }
        if (q < 33)       atomicMin(&g_min[q], enc(v));
        else if (q < 66)  atomicMax(&g_max[q - 33], enc(v));
        else              atomicAdd(&g_sum_abs, (double)v);
    }
}

// ---------------------------------------------------------------- pass 2: histograms
// Even CTAs handle the 16 u-features; odd CTAs the 16 s-features.
// 57.6 KB smem each -> 2 CTAs / SM.
__global__ void __launch_bounds__(1024, 2) k_hist(
    const float* __restrict__ yp, const float* __restrict__ u,
    const float* __restrict__ s, int N)
{
    extern __shared__ unsigned int sh[];   // 16 * NCELLS counters
    __shared__ float sinv[MMSLOTS], sbias[MMSLOTS];
    int tid = threadIdx.x;
    if (tid < MMSLOTS) {
        float lo = dec(g_min[tid]);
        float hi = dec(g_max[tid]);
        float iv = (float)NBINS / (hi - lo);
        sinv[tid]  = iv;
        sbias[tid] = -lo * iv;
    }
    for (int j = tid; j < 16 * NCELLS; j += blockDim.x) sh[j] = 0u;
    __syncthreads();

    int half = blockIdx.x & 1;                    // 0 -> u features, 1 -> s features
    const float* base = half ? s : u;
    int mmoff = half ? 17 : 1;

    int nb = gridDim.x >> 1;
    int stride = nb * blockDim.x;
    for (int i = (blockIdx.x >> 1) * blockDim.x + tid; i < N; i += stride) {
        float y = yp[i];
        int iy = binf2(y, sinv[0], sbias[0]);
        const float4* vr = reinterpret_cast<const float4*>(base) + (size_t)i * 4;
#pragma unroll
        for (int q = 0; q < 4; q++) {
            float4 v = vr[q];
            float vv[4] = {v.x, v.y, v.z, v.w};
#pragma unroll
            for (int k = 0; k < 4; k++) {
                int f = 4 * q + k;
                int ix = binf2(vv[k], sinv[mmoff + f], sbias[mmoff + f]);
                atomicAdd(&sh[f * NCELLS + ix * NBINS + iy], 1u);
            }
        }
    }
    __syncthreads();
    unsigned int* gh = g_hist + half * 16 * NCELLS;
    for (int j = tid; j < 16 * NCELLS; j += blockDim.x) {
        unsigned v = sh[j];
        if (v) atomicAdd(&gh[j], v);
    }
}

// ---------------------------------------------------------------- pass 3: MI per feature + final combine
__global__ void __launch_bounds__(256) k_mi(float* __restrict__ out, int N, int out_size) {
    __shared__ unsigned hcell[NCELLS];
    __shared__ float A[NBINS], B[NBINS];
    __shared__ double wred[8];
    __shared__ unsigned s_ticket;
    int tid = threadIdx.x, w = tid >> 5, lane = tid & 31;
    int f = blockIdx.x;

    const unsigned* h = g_hist + f * NCELLS;
    for (int j = tid; j < NCELLS; j += 256) hcell[j] = h[j];
    __syncthreads();

    if (tid < NBINS) {
        float ra = 0.0f;
#pragma unroll
        for (int j = 0; j < NBINS; j++) ra += (float)hcell[tid * NBINS + j];
        A[tid] = ra;
    } else if (tid >= 64 && tid < 64 + NBINS) {
        int c = tid - 64;
        float rb = 0.0f;
#pragma unroll
        for (int j = 0; j < NBINS; j++) rb += (float)hcell[j * NBINS + c];
        B[c] = rb;
    }
    __syncthreads();

    float invTot = 1.0f / (float)N;
    float mi = 0.0f;
    for (int c = tid; c < NCELLS; c += 256) {
        int i = c / NBINS, j = c - i * NBINS;
        float px = A[i] * invTot; if (px == 0.0f) px = 1e-10f;
        float py = B[j] * invTot; if (py == 0.0f) py = 1e-10f;
        unsigned cc = hcell[c];
        float pxy = cc ? (float)cc * invTot : 1e-10f;
        mi += pxy * __logf(pxy / (px * py));
    }
#pragma unroll
    for (int o = 16; o; o >>= 1) mi += __shfl_xor_sync(0xffffffffu, mi, o);
    if (lane == 0) wred[w] = (double)mi;
    __syncthreads();

    if (tid == 0) {
        double block_mi = 0.0;
        for (int k = 0; k < 8; k++) block_mi += wred[k];
        atomicAdd(&g_loss, 0.1 * block_mi);
        __threadfence();
        s_ticket = atomicAdd(&g_ticket, 1u);
    }
    __syncthreads();

    if (s_ticket == (unsigned)(gridDim.x - 1)) {
        // last block: all other blocks' g_loss contributions are visible
        for (int k = tid + 1; k < out_size; k += 256) out[k] = 0.0f;
        if (tid == 0) {
            double acc = g_loss + g_sum_abs / (double)N;
            for (int r = 0; r < 16; r++) acc -= 0.05 * g_mius[r];
            out[0] = (float)acc;
        }
    }
}

// ---------------------------------------------------------------- launch
extern "C" void kernel_launch(void* const* d_in, const int* in_sizes, int n_in,
                              void* d_out, int out_size) {
    const float* y_true = (const float*)d_in[0];
    const float* y_pred = (const float*)d_in[1];
    // d_in[2] = u_attr, d_in[3] = s_attr  (unused by the reference)
    const float* u_vec  = (const float*)d_in[4];
    const float* s_vec  = (const float*)d_in[5];
    int N = in_sizes[0];

    k_init<<<32, 256>>>(u_vec, s_vec);
    k_minmax<<<592, 256>>>(y_true, y_pred, u_vec, s_vec, N);

    size_t shbytes = (size_t)16 * NCELLS * sizeof(unsigned);          // 57.6 KB
    cudaFuncSetAttribute(k_hist, cudaFuncAttributeMaxDynamicSharedMemorySize, (int)shbytes);
    k_hist<<<296, 1024, shbytes>>>(y_pred, u_vec, s_vec, N);

    k_mi<<<32, 256>>>((float*)d_out, N, out_size);
}

// round 10
// speedup vs baseline: 1.4618x; 1.0229x over previous
#include <cuda_runtime.h>
#include <math.h>

#define NBINS 30
#define NCELLS (NBINS * NBINS)
#define NFEAT 32          // 16 u-columns + 16 s-columns
#define MMSLOTS 33        // y, u0..15, s0..15

__device__ unsigned int g_hist[NFEAT * NCELLS];
__device__ unsigned int g_min[MMSLOTS];
__device__ unsigned int g_max[MMSLOTS];
__device__ double g_sum_abs;
__device__ double g_mius[16];
__device__ unsigned int g_ticket;

// monotone float <-> uint mapping for atomicMin/Max
__device__ __forceinline__ unsigned enc(float f) {
    unsigned u = __float_as_uint(f);
    return (u & 0x80000000u) ? ~u : (u | 0x80000000u);
}
__device__ __forceinline__ float dec(unsigned u) {
    unsigned v = (u & 0x80000000u) ? (u ^ 0x80000000u) : ~u;
    return __uint_as_float(v);
}

__device__ __forceinline__ int binf2(float x, float iv, float bias) {
    int b = (int)floorf(fmaf(x, iv, bias));
    b = b < 0 ? 0 : b;
    return b > (NBINS - 1) ? (NBINS - 1) : b;
}

// ---------------------------------------------------------------- init + mi_us
__global__ void k_init(const float* __restrict__ u, const float* __restrict__ s) {
    int i = blockIdx.x * blockDim.x + threadIdx.x;
    int stride = gridDim.x * blockDim.x;
    for (int j = i; j < NFEAT * NCELLS; j += stride) g_hist[j] = 0u;
    if (i == 0) { g_sum_abs = 0.0; g_ticket = 0u; }
    if (i < MMSLOTS) { g_min[i] = 0xFFFFFFFFu; g_max[i] = 0u; }

    if (blockIdx.x < 16 && threadIdx.x < 32) {
        int r = blockIdx.x;
        int lane = threadIdx.x;
        int k = lane & 15;                 // sample index 0..15 (lanes 16..31 mirror)
        float uk = u[r * 16 + k];
        float sk = s[r * 16 + k];
        float umn = uk, umx = uk, smn2 = sk, smx2 = sk;
#pragma unroll
        for (int o = 8; o; o >>= 1) {
            umn  = fminf(umn,  __shfl_xor_sync(0xffffffffu, umn,  o));
            umx  = fmaxf(umx,  __shfl_xor_sync(0xffffffffu, umx,  o));
            smn2 = fminf(smn2, __shfl_xor_sync(0xffffffffu, smn2, o));
            smx2 = fmaxf(smx2, __shfl_xor_sync(0xffffffffu, smx2, o));
        }
        float ustep = (umx - umn) / 29.0f;
        float sstep = (smx2 - smn2) / 29.0f;
        int cu = 0, cs = 0;
#pragma unroll
        for (int j = 0; j < 30; j++) {
            float eu = (j == 29) ? umx  : __fadd_rn(umn,  __fmul_rn((float)j, ustep));
            float es = (j == 29) ? smx2 : __fadd_rn(smn2, __fmul_rn((float)j, sstep));
            cu += (eu <= uk);
            cs += (es <= sk);
        }
        int lus[16], lss[16];
#pragma unroll
        for (int m = 0; m < 16; m++) {
            lus[m] = __shfl_sync(0xffffffffu, cu, m);
            lss[m] = __shfl_sync(0xffffffffu, cs, m);
        }
        float mi = 0.0f;
        if (lane < 16) {
            bool first = true;
            for (int m = 0; m < k; m++)
                if (lus[m] == cu && lss[m] == cs) { first = false; break; }
            if (first) {
                int C = 0, A = 0, B = 0;
#pragma unroll
                for (int m = 0; m < 16; m++) {
                    int eq_u = (lus[m] == cu);
                    int eq_s = (lss[m] == cs);
                    C += eq_u & eq_s;
                    A += eq_u;
                    B += eq_s;
                }
                mi = ((float)C * (1.0f / 16.0f)) * __logf(((float)(C * 16)) / ((float)(A * B)));
            }
        }
#pragma unroll
        for (int o = 8; o; o >>= 1) mi += __shfl_xor_sync(0x0000ffffu, mi, o);
        if (lane == 0) g_mius[r] = (double)mi;
    }
}

// ---------------------------------------------------------------- pass 1: min/max + L1
__global__ void __launch_bounds__(256) k_minmax(
    const float* __restrict__ yt, const float* __restrict__ yp,
    const float* __restrict__ u, const float* __restrict__ s, int N)
{
    float ymn = INFINITY, ymx = -INFINITY;
    float umn[16], umx[16], smn[16], smx[16];
#pragma unroll
    for (int f = 0; f < 16; f++) {
        umn[f] = INFINITY; umx[f] = -INFINITY;
        smn[f] = INFINITY; smx[f] = -INFINITY;
    }
    float sab = 0.0f;

    int stride = gridDim.x * blockDim.x;
    for (int i = blockIdx.x * blockDim.x + threadIdx.x; i < N; i += stride) {
        float a = yt[i], b = yp[i];
        sab += fabsf(a - b);
        ymn = fminf(ymn, b); ymx = fmaxf(ymx, b);
        const float4* ur = reinterpret_cast<const float4*>(u) + (size_t)i * 4;
        const float4* sr = reinterpret_cast<const float4*>(s) + (size_t)i * 4;
#pragma unroll
        for (int q = 0; q < 4; q++) {
            float4 uv = ur[q];
            float4 sv = sr[q];
            umn[4*q+0] = fminf(umn[4*q+0], uv.x); umx[4*q+0] = fmaxf(umx[4*q+0], uv.x);
            umn[4*q+1] = fminf(umn[4*q+1], uv.y); umx[4*q+1] = fmaxf(umx[4*q+1], uv.y);
            umn[4*q+2] = fminf(umn[4*q+2], uv.z); umx[4*q+2] = fmaxf(umx[4*q+2], uv.z);
            umn[4*q+3] = fminf(umn[4*q+3], uv.w); umx[4*q+3] = fmaxf(umx[4*q+3], uv.w);
            smn[4*q+0] = fminf(smn[4*q+0], sv.x); smx[4*q+0] = fmaxf(smx[4*q+0], sv.x);
            smn[4*q+1] = fminf(smn[4*q+1], sv.y); smx[4*q+1] = fmaxf(smx[4*q+1], sv.y);
            smn[4*q+2] = fminf(smn[4*q+2], sv.z); smx[4*q+2] = fmaxf(smx[4*q+2], sv.z);
            smn[4*q+3] = fminf(smn[4*q+3], sv.w); smx[4*q+3] = fmaxf(smx[4*q+3], sv.w);
        }
    }

    // gather into one indexed array: [0..32]=mins(y,u,s) [33..65]=maxes [66]=sum
    float all[67];
    all[0] = ymn; all[33] = ymx;
#pragma unroll
    for (int f = 0; f < 16; f++) {
        all[1 + f]  = umn[f]; all[17 + f] = smn[f];
        all[34 + f] = umx[f]; all[50 + f] = smx[f];
    }
    all[66] = sab;

    __shared__ float red[67 * 8];
    int wid = threadIdx.x >> 5, lane = threadIdx.x & 31;
#pragma unroll
    for (int q = 0; q < 67; q++) {
        float v = all[q];
#pragma unroll
        for (int o = 16; o; o >>= 1) {
            float other = __shfl_xor_sync(0xffffffffu, v, o);
            v = (q < 33) ? fminf(v, other) : (q < 66 ? fmaxf(v, other) : v + other);
        }
        if (lane == 0) red[q * 8 + wid] = v;
    }
    __syncthreads();
    if (threadIdx.x < 67) {
        int q = threadIdx.x;
        float v = red[q * 8];
        for (int w = 1; w < 8; w++) {
            float o = red[q * 8 + w];
            v = (q < 33) ? fminf(v, o) : (q < 66 ? fmaxf(v, o) : v + o);
        }
        if (q < 33)       atomicMin(&g_min[q], enc(v));
        else if (q < 66)  atomicMax(&g_max[q - 33], enc(v));
        else              atomicAdd(&g_sum_abs, (double)v);
    }
}

// ---------------------------------------------------------------- pass 2: histograms + fused MI tail
// 4-way feature split: blockIdx%4 -> {u0-7, u8-15, s0-7, s8-15}.
// 8 features per CTA, 28.8 KB smem -> 4 CTAs/SM, 512 threads each.
// Last CTA to finish (ticket) computes all 32 MI terms + final combine.
__global__ void __launch_bounds__(512, 4) k_hist(
    const float* __restrict__ yp, const float* __restrict__ u,
    const float* __restrict__ s, int N,
    float* __restrict__ out, int out_size)
{
    extern __shared__ unsigned int sh[];   // 8 * NCELLS counters
    __shared__ float sinv[MMSLOTS], sbias[MMSLOTS];
    __shared__ unsigned s_ticket;
    int tid = threadIdx.x;
    if (tid < MMSLOTS) {
        float lo = dec(g_min[tid]);
        float hi = dec(g_max[tid]);
        float iv = (float)NBINS / (hi - lo);
        sinv[tid]  = iv;
        sbias[tid] = -lo * iv;
    }
    for (int j = tid; j < 8 * NCELLS; j += blockDim.x) sh[j] = 0u;
    __syncthreads();

    int quarter = blockIdx.x & 3;                 // 0:u-lo 1:u-hi 2:s-lo 3:s-hi
    const float* base = (quarter & 2) ? s : u;
    int sub = (quarter & 1) * 8;                  // feature offset within the 16
    int mmoff = ((quarter & 2) ? 17 : 1) + sub;
    int featbase = quarter * 8;                   // global feature index base

    int nb = gridDim.x >> 2;
    int stride = nb * blockDim.x;
    for (int i = (blockIdx.x >> 2) * blockDim.x + tid; i < N; i += stride) {
        float y = yp[i];
        int iy = binf2(y, sinv[0], sbias[0]);
        const float4* vr = reinterpret_cast<const float4*>(base + (size_t)i * 16 + sub);
        float4 v0 = vr[0];
        float4 v1 = vr[1];
        float vv[8] = {v0.x, v0.y, v0.z, v0.w, v1.x, v1.y, v1.z, v1.w};
#pragma unroll
        for (int k = 0; k < 8; k++) {
            int ix = binf2(vv[k], sinv[mmoff + k], sbias[mmoff + k]);
            atomicAdd(&sh[k * NCELLS + ix * NBINS + iy], 1u);
        }
    }
    __syncthreads();

    unsigned int* gh = g_hist + featbase * NCELLS;
    for (int j = tid; j < 8 * NCELLS; j += blockDim.x) {
        unsigned v = sh[j];
        if (v) atomicAdd(&gh[j], v);
    }
    __threadfence();
    __syncthreads();
    if (tid == 0) s_ticket = atomicAdd(&g_ticket, 1u);
    __syncthreads();
    if (s_ticket != (unsigned)(gridDim.x - 1)) return;

    // ---------------- last CTA: all 32 histograms are complete & L2-hot ----------------
    __shared__ float Am[NFEAT][NBINS], Bm[NFEAT][NBINS];
    __shared__ double wsum[16];
    int w = tid >> 5, lane = tid & 31;

    double my = 0.0;
#pragma unroll
    for (int fi = 0; fi < 2; fi++) {
        int f = 2 * w + fi;
        const unsigned* h = g_hist + f * NCELLS;
        if (lane < NBINS) {
            float ra = 0.0f, rb = 0.0f;
#pragma unroll
            for (int j = 0; j < NBINS; j++) {
                ra += (float)h[lane * NBINS + j];
                rb += (float)h[j * NBINS + lane];
            }
            Am[f][lane] = ra;
            Bm[f][lane] = rb;
        }
        __syncwarp();
        float invTot = 1.0f / (float)N;
        float mi = 0.0f;
        for (int c = lane; c < NCELLS; c += 32) {
            int i = c / NBINS, j = c - i * NBINS;
            float px = Am[f][i] * invTot; if (px == 0.0f) px = 1e-10f;
            float py = Bm[f][j] * invTot; if (py == 0.0f) py = 1e-10f;
            unsigned cc = h[c];
            float pxy = cc ? (float)cc * invTot : 1e-10f;
            mi += pxy * __logf(pxy / (px * py));
        }
#pragma unroll
        for (int o = 16; o; o >>= 1) mi += __shfl_xor_sync(0xffffffffu, mi, o);
        my += (double)mi;
    }
    if (lane == 0) wsum[w] = my;
    __syncthreads();

    for (int k = tid + 1; k < out_size; k += blockDim.x) out[k] = 0.0f;
    if (tid == 0) {
        double acc = 0.0;
        for (int k = 0; k < 16; k++) acc += wsum[k];
        acc = 0.1 * acc + g_sum_abs / (double)N;
        for (int r = 0; r < 16; r++) acc -= 0.05 * g_mius[r];
        out[0] = (float)acc;
    }
}

// ---------------------------------------------------------------- launch
extern "C" void kernel_launch(void* const* d_in, const int* in_sizes, int n_in,
                              void* d_out, int out_size) {
    const float* y_true = (const float*)d_in[0];
    const float* y_pred = (const float*)d_in[1];
    // d_in[2] = u_attr, d_in[3] = s_attr  (unused by the reference)
    const float* u_vec  = (const float*)d_in[4];
    const float* s_vec  = (const float*)d_in[5];
    int N = in_sizes[0];

    k_init<<<32, 256>>>(u_vec, s_vec);
    k_minmax<<<592, 256>>>(y_true, y_pred, u_vec, s_vec, N);

    size_t shbytes = (size_t)8 * NCELLS * sizeof(unsigned);           // 28.8 KB
    cudaFuncSetAttribute(k_hist, cudaFuncAttributeMaxDynamicSharedMemorySize, (int)shbytes);
    k_hist<<<592, 512, shbytes>>>(y_pred, u_vec, s_vec, N, (float*)d_out, out_size);
}